// round 9
// baseline (speedup 1.0000x reference)
#include <cuda_runtime.h>
#include <math.h>

#define JW 10
#define DCH 100          // days per chunk (T=50000 -> 500 chunks)
#define MAXCH 512

// Cross-block publication (allocation-free rule: __device__ globals).
// g_valid is zero-initialized at module load; once set it stays set, and
// g_clog values are bit-identical every call (pure function of the inputs),
// so replays never spin and any concurrent rewrite is a benign identical-
// value race on aligned 32-bit words.
__device__ float g_clog[MAXCH];
__device__ int   g_valid[MAXCH];

typedef unsigned long long u64;

// ---- packed f32x2 helpers (sm_103a) ----
__device__ __forceinline__ u64 pk2(float lo, float hi) {
    u64 r; asm("mov.b64 %0, {%1, %2};" : "=l"(r) : "f"(lo), "f"(hi)); return r;
}
__device__ __forceinline__ u64 mul2(u64 a, u64 b) {
    u64 d; asm("mul.rn.f32x2 %0, %1, %2;" : "=l"(d) : "l"(a), "l"(b)); return d;
}
__device__ __forceinline__ u64 fma2(u64 a, u64 b, u64 c) {
    u64 d; asm("fma.rn.f32x2 %0, %1, %2, %3;" : "=l"(d) : "l"(a), "l"(b), "l"(c)); return d;
}
__device__ __forceinline__ u64 add2(u64 a, u64 b) {
    u64 d; asm("add.rn.f32x2 %0, %1, %2;" : "=l"(d) : "l"(a), "l"(b)); return d;
}
// 16-byte streaming store: two packed f32x2 (4 consecutive samples)
__device__ __forceinline__ void stcs128(u64* p, u64 lo, u64 hi) {
    asm volatile("st.global.cs.v2.b64 [%0], {%1, %2};"
                 :: "l"(p), "l"(lo), "l"(hi) : "memory");
}

// ---- fused kernel: per-chunk log-product publication + main compute ----
// Producer (block x==0 of chunk c): g_clog[c] = log(prod of r over chunk c),
// computed as a double product (exact to ~1e-15) + one __logf (abs 2e-7).
// Consumer (any block, c>0): anchor Pex = sum_{k<c} g_clog[k].
// A[d,s] = wlast[s]*exp(Pex*invT[s]) at the chunk start (via __expf), then
// day steps use the binomial poly (1+v)^t ~= 1 + t v + t(t-1)/2 v^2 on r
// directly; window init walks backward with (1+v)^(-t) (degree-3).
// M[d,s] = sum_j (rho*pi[j,s]) * A_ext[J+d-1-j, s]
__global__ void __launch_bounds__(128, 3) main_kernel(
    const float* __restrict__ r,      // (T,)
    const float* __restrict__ warm,   // (J,S)
    const float* __restrict__ Ts,     // (S,)
    const float* __restrict__ rho,    // (S,)
    const float* __restrict__ pi,     // (J,S)
    u64* __restrict__ out,            // (T, S/2) packed f32x2
    int T, int S)
{
    __shared__ double sd[128];
    __shared__ float  sf[128];

    const int tid = threadIdx.x;
    const int c   = blockIdx.y;
    const int d0  = c * DCH;
    const int nch = gridDim.y;
    (void)nch;

    // ---- producer: publish this chunk's log-multiplier (x==0 blocks) ----
    if (blockIdx.x == 0) {
        double dp = 1.0;
        int i = d0 + 2 * tid;
        if (2 * tid < DCH && i + 1 < T) {
            float2 rv = *(const float2*)(r + i);    // d0 is 400B-aligned
            dp = (double)rv.x * (double)rv.y;
        } else if (2 * tid < DCH && i < T) {
            dp = (double)r[i];
        }
        sd[tid] = dp;
        __syncthreads();
#pragma unroll
        for (int off = 64; off > 0; off >>= 1) {
            if (tid < off) sd[tid] *= sd[tid + off];
            __syncthreads();
        }
        if (tid == 0) {
            g_clog[c] = __logf((float)sd[0]);
            __threadfence();
            ((volatile int*)g_valid)[c] = 1;
        }
    }

    // ---- consumer: wait for + sum prefix log-multipliers ----
    float Pex = 0.0f;
    if (c > 0) {
        int ok;
        do {
            int mine = 1;
            for (int k = tid; k < c; k += 128)
                mine &= ((volatile int*)g_valid)[k];
            ok = __syncthreads_and(mine);
            if (!ok) __nanosleep(200);
        } while (!ok);
        __threadfence();

        float s = 0.0f;
        for (int k = tid; k < c; k += 128) s += g_clog[k];
        sf[tid] = s;
        __syncthreads();
#pragma unroll
        for (int off = 64; off > 0; off >>= 1) {
            if (tid < off) sf[tid] += sf[tid + off];
            __syncthreads();
        }
        Pex = sf[0];                         // sum log r[0..d0-1]
    }
    __syncthreads();

    // ---- main compute: QS=4 samples/thread, two f32x2 windows, STG.128 ----
    int q = blockIdx.x * blockDim.x + tid;   // quad index
    int nquads = S >> 2;
    if (q >= nquads) return;

    float4 Ts4  = ((const float4*)Ts)[q];
    float4 rho4 = ((const float4*)rho)[q];
    float t0 = 1.0f / Ts4.x, t1 = 1.0f / Ts4.y;
    float t2 = 1.0f / Ts4.z, t3 = 1.0f / Ts4.w;

    u64 pirA[JW], pirB[JW];
#pragma unroll
    for (int j = 0; j < JW; ++j) {
        float4 p4 = ((const float4*)(pi + j * S))[q];
        pirA[j] = pk2(p4.x * rho4.x, p4.y * rho4.y);
        pirB[j] = pk2(p4.z * rho4.z, p4.w * rho4.w);
    }

    const u64 C1A = pk2(t0, t1), C1B = pk2(t2, t3);
    const u64 C2A = pk2(0.5f * t0 * (t0 - 1.0f), 0.5f * t1 * (t1 - 1.0f));
    const u64 C2B = pk2(0.5f * t2 * (t2 - 1.0f), 0.5f * t3 * (t3 - 1.0f));
    const u64 ONE2 = pk2(1.0f, 1.0f);

    u64 winA[JW], winB[JW];
    if (c == 0) {
#pragma unroll
        for (int j = 0; j < JW; ++j) {
            float4 w4 = ((const float4*)(warm + (JW - 1 - j) * S))[q];
            winA[j] = pk2(w4.x, w4.y);
            winB[j] = pk2(w4.z, w4.w);
        }
    } else {
        float4 wl4 = ((const float4*)(warm + (JW - 1) * S))[q];
        winA[0] = pk2(wl4.x * __expf(Pex * t0), wl4.y * __expf(Pex * t1));
        winB[0] = pk2(wl4.z * __expf(Pex * t2), wl4.w * __expf(Pex * t3));
        // backward walk: (1+v)^(-t) ~= 1 - t v + t(t+1)/2 v^2 - t(t+1)(t+2)/6 v^3
        u64 B1A = pk2(-t0, -t1), B1B = pk2(-t2, -t3);
        u64 B2A = pk2(0.5f * t0 * (t0 + 1.0f), 0.5f * t1 * (t1 + 1.0f));
        u64 B2B = pk2(0.5f * t2 * (t2 + 1.0f), 0.5f * t3 * (t3 + 1.0f));
        u64 B3A = pk2(-t0 * (t0 + 1.0f) * (t0 + 2.0f) / 6.0f,
                      -t1 * (t1 + 1.0f) * (t1 + 2.0f) / 6.0f);
        u64 B3B = pk2(-t2 * (t2 + 1.0f) * (t2 + 2.0f) / 6.0f,
                      -t3 * (t3 + 1.0f) * (t3 + 2.0f) / 6.0f);
#pragma unroll
        for (int j = 1; j < JW; ++j) {
            float v = r[d0 - j] - 1.0f;
            u64 v2 = pk2(v, v);
            u64 eA = fma2(v2, fma2(v2, fma2(v2, B3A, B2A), B1A), ONE2);
            u64 eB = fma2(v2, fma2(v2, fma2(v2, B3B, B2B), B1B), ONE2);
            winA[j] = mul2(winA[j - 1], eA);
            winB[j] = mul2(winB[j - 1], eB);
        }
    }
    u64 aA = winA[0], aB = winB[0];

    const float4* R4 = (const float4*)(r + d0);   // d0*4B is 400B-aligned
    u64* o = out + ((size_t)d0 * nquads + q) * 2;
    const size_t ostep = (size_t)nquads * 2;

#define STEP(rv) do {                                               \
        u64 mA0 = mul2(pirA[0], winA[0]);                           \
        u64 mA1 = mul2(pirA[1], winA[1]);                           \
        u64 mB0 = mul2(pirB[0], winB[0]);                           \
        u64 mB1 = mul2(pirB[1], winB[1]);                           \
        mA0 = fma2(pirA[2], winA[2], mA0);                          \
        mA1 = fma2(pirA[3], winA[3], mA1);                          \
        mB0 = fma2(pirB[2], winB[2], mB0);                          \
        mB1 = fma2(pirB[3], winB[3], mB1);                          \
        mA0 = fma2(pirA[4], winA[4], mA0);                          \
        mA1 = fma2(pirA[5], winA[5], mA1);                          \
        mB0 = fma2(pirB[4], winB[4], mB0);                          \
        mB1 = fma2(pirB[5], winB[5], mB1);                          \
        mA0 = fma2(pirA[6], winA[6], mA0);                          \
        mA1 = fma2(pirA[7], winA[7], mA1);                          \
        mB0 = fma2(pirB[6], winB[6], mB0);                          \
        mB1 = fma2(pirB[7], winB[7], mB1);                          \
        mA0 = fma2(pirA[8], winA[8], mA0);                          \
        mA1 = fma2(pirA[9], winA[9], mA1);                          \
        mB0 = fma2(pirB[8], winB[8], mB0);                          \
        mB1 = fma2(pirB[9], winB[9], mB1);                          \
        stcs128(o, add2(mA0, mA1), add2(mB0, mB1));                 \
        o += ostep;                                                 \
        float vv = (rv) - 1.0f;                                     \
        u64 v2 = pk2(vv, vv);                                       \
        u64 eA = fma2(v2, fma2(v2, C2A, C1A), ONE2);                \
        u64 eB = fma2(v2, fma2(v2, C2B, C1B), ONE2);                \
        aA = mul2(aA, eA);                                          \
        aB = mul2(aB, eB);                                          \
        _Pragma("unroll")                                           \
        for (int j = JW - 1; j > 0; --j) {                          \
            winA[j] = winA[j - 1];                                  \
            winB[j] = winB[j - 1];                                  \
        }                                                           \
        winA[0] = aA;                                               \
        winB[0] = aB;                                               \
    } while (0)

    if (d0 + DCH <= T) {
        // 25 iters of 4 days; unroll 5 -> 20 days/body = 2 full window rotations
#pragma unroll 5
        for (int it = 0; it < DCH / 4; ++it) {
            float4 L = R4[it];
            STEP(L.x);
            STEP(L.y);
            STEP(L.z);
            STEP(L.w);
        }
    } else {
        for (int d = d0; d < T; ++d) {
            float rv = r[d];
            STEP(rv);
        }
    }
#undef STEP
}

extern "C" void kernel_launch(void* const* d_in, const int* in_sizes, int n_in,
                              void* d_out, int out_size) {
    const float* r    = (const float*)d_in[0];  // (1,T)
    const float* warm = (const float*)d_in[1];  // (J,S)
    const float* Ts   = (const float*)d_in[2];  // (S,)
    const float* rho  = (const float*)d_in[3];  // (S,)
    const float* pi   = (const float*)d_in[4];  // (J,S)

    int T = in_sizes[0];
    int S = in_sizes[2];
    int nch = (T + DCH - 1) / DCH;

    int nquads = S / 4;
    dim3 grid((nquads + 127) / 128, nch);
    main_kernel<<<grid, 128>>>(r, warm, Ts, rho, pi, (u64*)d_out, T, S);
}

// round 10
// speedup vs baseline: 1.0376x; 1.0376x over previous
#include <cuda_runtime.h>
#include <math.h>

#define JW 10
#define DCH 100          // days per chunk (T=50000 -> 500 chunks)
#define MAXCH 1024

// Scratch (allocation-free rule: __device__ globals)
__device__ float g_Pex[MAXCH];   // exclusive prefix of log r at chunk starts

typedef unsigned long long u64;

// ---- packed f32x2 helpers (sm_103a) ----
__device__ __forceinline__ u64 pk2(float lo, float hi) {
    u64 r; asm("mov.b64 %0, {%1, %2};" : "=l"(r) : "f"(lo), "f"(hi)); return r;
}
__device__ __forceinline__ u64 mul2(u64 a, u64 b) {
    u64 d; asm("mul.rn.f32x2 %0, %1, %2;" : "=l"(d) : "l"(a), "l"(b)); return d;
}
__device__ __forceinline__ u64 fma2(u64 a, u64 b, u64 c) {
    u64 d; asm("fma.rn.f32x2 %0, %1, %2, %3;" : "=l"(d) : "l"(a), "l"(b), "l"(c)); return d;
}
__device__ __forceinline__ u64 add2(u64 a, u64 b) {
    u64 d; asm("add.rn.f32x2 %0, %1, %2;" : "=l"(d) : "l"(a), "l"(b)); return d;
}
// 16-byte streaming store: two packed f32x2 (4 consecutive samples)
__device__ __forceinline__ void stcs128(u64* p, u64 lo, u64 hi) {
    asm volatile("st.global.cs.v2.b64 [%0], {%1, %2};"
                 :: "l"(p), "l"(lo), "l"(hi) : "memory");
}

// log(1+x), |x| <= ~0.011: degree-5 poly, abs err ~1e-9
__device__ __forceinline__ float log1p_poly(float x) {
    float p = fmaf(x, 0.2f, -0.25f);
    p = fmaf(x, p, 1.0f / 3.0f);
    p = fmaf(x, p, -0.5f);
    p = fmaf(x, p, 1.0f);
    return x * p;
}

// ---- prep (single block, coalesced) — R8-proven anchor computation ----
__global__ void __launch_bounds__(1024) prep_kernel(const float* __restrict__ r,
                                                    int T, int nch) {
    // PDL: allow the dependent (main) grid to begin scheduling immediately;
    // its griddepcontrol.wait still blocks until this grid fully completes.
    asm volatile("griddepcontrol.launch_dependents;" ::: "memory");

    __shared__ float s8[6272];    // 8-day log-sums: ceil(T/8) <= 6250
    __shared__ float cs[512];     // 200-day super-chunk sums
    int t = threadIdx.x;

    int n4 = (T + 3) >> 2;        // # float4 groups (T=50000 -> 12500)
    int n8 = (T + 7) >> 3;        // # 8-day groups  (6250)

    for (int k = 0; k < (n4 + 1023) / 1024; ++k) {
        int i4 = k * 1024 + t;
        float v = 0.0f;
        if (i4 < n4) {
            int d = i4 * 4;
            if (d + 4 <= T) {
                float4 rv = *(const float4*)(r + d);   // coalesced
                v = (log1p_poly(rv.x - 1.0f) + log1p_poly(rv.y - 1.0f))
                  + (log1p_poly(rv.z - 1.0f) + log1p_poly(rv.w - 1.0f));
            } else {
                for (int i = d; i < T; ++i) v += log1p_poly(r[i] - 1.0f);
            }
        }
        float w = v + __shfl_xor_sync(0xffffffffu, v, 1);
        int i8 = i4 >> 1;
        if ((t & 1) == 0 && i4 < n4 && i8 < n8) s8[i8] = w;
    }
    __syncthreads();

    // 200-day super-chunk sums (25 x 8-day groups each)
    if (t < 512) {
        float s = 0.0f;
        int c2 = t;
        if (c2 < (nch + 1) / 2) {
            int base = c2 * 25;
            float a0 = 0.f, a1 = 0.f, a2 = 0.f, a3 = 0.f, a4 = 0.f;
#pragma unroll
            for (int i = 0; i < 25; i += 5) {
                a0 += s8[base + i];
                a1 += s8[base + i + 1];
                a2 += s8[base + i + 2];
                a3 += s8[base + i + 3];
                a4 += s8[base + i + 4];
            }
            s = ((a0 + a1) + (a2 + a3)) + a4;
        }
        cs[t] = s;
    }
    __syncthreads();

    // Hillis-Steele inclusive scan over 512 super-chunk sums
#pragma unroll
    for (int off = 1; off < 512; off <<= 1) {
        float u = 0.0f;
        if (t < 512 && t >= off) u = cs[t - off];
        __syncthreads();
        if (t < 512) cs[t] += u;
        __syncthreads();
    }
    // emit 100-day-chunk exclusive prefixes
    if (t < nch) {
        int c2 = t >> 1;
        float superExcl = (c2 == 0) ? 0.0f : cs[c2 - 1];
        if ((t & 1) == 0) {
            g_Pex[t] = superExcl;
        } else {
            // + first 100 days of super-chunk c2: 12 x 8-day + 4 days from r
            float h = 0.0f;
            int b = c2 * 25;
#pragma unroll
            for (int i = 0; i < 12; ++i) h += s8[b + i];
            int d = (c2 * 200) + 96;
            h += (log1p_poly(r[d] - 1.0f) + log1p_poly(r[d + 1] - 1.0f))
               + (log1p_poly(r[d + 2] - 1.0f) + log1p_poly(r[d + 3] - 1.0f));
            g_Pex[t] = superExcl + h;
        }
    }
}

// ---- main kernel: QS=4 samples/thread, two f32x2 windows, STG.128 ----
// Identical compute to R8 (measured 38.7us); adds griddepcontrol.wait
// before the only read of prep-produced data (g_Pex).
__global__ void __launch_bounds__(128) main_kernel(
    const float* __restrict__ r,      // (T,)
    const float* __restrict__ warm,   // (J,S)
    const float* __restrict__ Ts,     // (S,)
    const float* __restrict__ rho,    // (S,)
    const float* __restrict__ pi,     // (J,S)
    u64* __restrict__ out,            // (T, S/2) packed f32x2
    int T, int S)
{
    int q = blockIdx.x * blockDim.x + threadIdx.x;   // quad index
    int nquads = S >> 2;
    if (q >= nquads) {
        // keep PDL semantics clean for exiting threads
        asm volatile("griddepcontrol.wait;" ::: "memory");
        return;
    }
    int c  = blockIdx.y;
    int d0 = c * DCH;

    float4 Ts4  = ((const float4*)Ts)[q];
    float4 rho4 = ((const float4*)rho)[q];
    float t0 = 1.0f / Ts4.x, t1 = 1.0f / Ts4.y;
    float t2 = 1.0f / Ts4.z, t3 = 1.0f / Ts4.w;

    u64 pirA[JW], pirB[JW];
#pragma unroll
    for (int j = 0; j < JW; ++j) {
        float4 p4 = ((const float4*)(pi + j * S))[q];
        pirA[j] = pk2(p4.x * rho4.x, p4.y * rho4.y);
        pirB[j] = pk2(p4.z * rho4.z, p4.w * rho4.w);
    }

    const u64 C1A = pk2(t0, t1), C1B = pk2(t2, t3);
    const u64 C2A = pk2(0.5f * t0 * (t0 - 1.0f), 0.5f * t1 * (t1 - 1.0f));
    const u64 C2B = pk2(0.5f * t2 * (t2 - 1.0f), 0.5f * t3 * (t3 - 1.0f));
    const u64 ONE2 = pk2(1.0f, 1.0f);

    u64 winA[JW], winB[JW];
    if (c == 0) {
#pragma unroll
        for (int j = 0; j < JW; ++j) {
            float4 w4 = ((const float4*)(warm + (JW - 1 - j) * S))[q];
            winA[j] = pk2(w4.x, w4.y);
            winB[j] = pk2(w4.z, w4.w);
        }
        asm volatile("griddepcontrol.wait;" ::: "memory");  // no prep data used
    } else {
        float4 wl4 = ((const float4*)(warm + (JW - 1) * S))[q];
        // prep-produced anchor: block until prep has completed (PDL edge)
        asm volatile("griddepcontrol.wait;" ::: "memory");
        float Pex = g_Pex[c];                 // sum log r[0..d0-1]
        winA[0] = pk2(wl4.x * __expf(Pex * t0), wl4.y * __expf(Pex * t1));
        winB[0] = pk2(wl4.z * __expf(Pex * t2), wl4.w * __expf(Pex * t3));
        // backward walk: (1+v)^(-t) ~= 1 - t v + t(t+1)/2 v^2 - t(t+1)(t+2)/6 v^3
        u64 B1A = pk2(-t0, -t1), B1B = pk2(-t2, -t3);
        u64 B2A = pk2(0.5f * t0 * (t0 + 1.0f), 0.5f * t1 * (t1 + 1.0f));
        u64 B2B = pk2(0.5f * t2 * (t2 + 1.0f), 0.5f * t3 * (t3 + 1.0f));
        u64 B3A = pk2(-t0 * (t0 + 1.0f) * (t0 + 2.0f) / 6.0f,
                      -t1 * (t1 + 1.0f) * (t1 + 2.0f) / 6.0f);
        u64 B3B = pk2(-t2 * (t2 + 1.0f) * (t2 + 2.0f) / 6.0f,
                      -t3 * (t3 + 1.0f) * (t3 + 2.0f) / 6.0f);
#pragma unroll
        for (int j = 1; j < JW; ++j) {
            float v = r[d0 - j] - 1.0f;
            u64 v2 = pk2(v, v);
            u64 eA = fma2(v2, fma2(v2, fma2(v2, B3A, B2A), B1A), ONE2);
            u64 eB = fma2(v2, fma2(v2, fma2(v2, B3B, B2B), B1B), ONE2);
            winA[j] = mul2(winA[j - 1], eA);
            winB[j] = mul2(winB[j - 1], eB);
        }
    }
    u64 aA = winA[0], aB = winB[0];

    const float4* R4 = (const float4*)(r + d0);   // d0*4B is 400B-aligned
    u64* o = out + ((size_t)d0 * nquads + q) * 2;
    const size_t ostep = (size_t)nquads * 2;

#define STEP(rv) do {                                               \
        u64 mA0 = mul2(pirA[0], winA[0]);                           \
        u64 mA1 = mul2(pirA[1], winA[1]);                           \
        u64 mB0 = mul2(pirB[0], winB[0]);                           \
        u64 mB1 = mul2(pirB[1], winB[1]);                           \
        mA0 = fma2(pirA[2], winA[2], mA0);                          \
        mA1 = fma2(pirA[3], winA[3], mA1);                          \
        mB0 = fma2(pirB[2], winB[2], mB0);                          \
        mB1 = fma2(pirB[3], winB[3], mB1);                          \
        mA0 = fma2(pirA[4], winA[4], mA0);                          \
        mA1 = fma2(pirA[5], winA[5], mA1);                          \
        mB0 = fma2(pirB[4], winB[4], mB0);                          \
        mB1 = fma2(pirB[5], winB[5], mB1);                          \
        mA0 = fma2(pirA[6], winA[6], mA0);                          \
        mA1 = fma2(pirA[7], winA[7], mA1);                          \
        mB0 = fma2(pirB[6], winB[6], mB0);                          \
        mB1 = fma2(pirB[7], winB[7], mB1);                          \
        mA0 = fma2(pirA[8], winA[8], mA0);                          \
        mA1 = fma2(pirA[9], winA[9], mA1);                          \
        mB0 = fma2(pirB[8], winB[8], mB0);                          \
        mB1 = fma2(pirB[9], winB[9], mB1);                          \
        stcs128(o, add2(mA0, mA1), add2(mB0, mB1));                 \
        o += ostep;                                                 \
        float vv = (rv) - 1.0f;                                     \
        u64 v2 = pk2(vv, vv);                                       \
        u64 eA = fma2(v2, fma2(v2, C2A, C1A), ONE2);                \
        u64 eB = fma2(v2, fma2(v2, C2B, C1B), ONE2);                \
        aA = mul2(aA, eA);                                          \
        aB = mul2(aB, eB);                                          \
        _Pragma("unroll")                                           \
        for (int j = JW - 1; j > 0; --j) {                          \
            winA[j] = winA[j - 1];                                  \
            winB[j] = winB[j - 1];                                  \
        }                                                           \
        winA[0] = aA;                                               \
        winB[0] = aB;                                               \
    } while (0)

    if (d0 + DCH <= T) {
        // 25 iters of 4 days; unroll 5 -> 20 days/body = 2 full window rotations
#pragma unroll 5
        for (int it = 0; it < DCH / 4; ++it) {
            float4 L = R4[it];
            STEP(L.x);
            STEP(L.y);
            STEP(L.z);
            STEP(L.w);
        }
    } else {
        for (int d = d0; d < T; ++d) {
            float rv = r[d];
            STEP(rv);
        }
    }
#undef STEP
}

extern "C" void kernel_launch(void* const* d_in, const int* in_sizes, int n_in,
                              void* d_out, int out_size) {
    const float* r    = (const float*)d_in[0];  // (1,T)
    const float* warm = (const float*)d_in[1];  // (J,S)
    const float* Ts   = (const float*)d_in[2];  // (S,)
    const float* rho  = (const float*)d_in[3];  // (S,)
    const float* pi   = (const float*)d_in[4];  // (J,S)

    int T = in_sizes[0];
    int S = in_sizes[2];
    int nch = (T + DCH - 1) / DCH;

    prep_kernel<<<1, 1024>>>(r, T, nch);

    int nquads = S / 4;
    dim3 grid((nquads + 127) / 128, nch);

    // PDL launch of main: may begin scheduling while prep runs; the
    // griddepcontrol.wait inside orders the g_Pex read after prep completes.
    cudaLaunchConfig_t cfg = {};
    cfg.gridDim = grid;
    cfg.blockDim = dim3(128, 1, 1);
    cfg.dynamicSmemBytes = 0;
    cfg.stream = 0;
    cudaLaunchAttribute at[1];
    at[0].id = cudaLaunchAttributeProgrammaticStreamSerialization;
    at[0].val.programmaticStreamSerializationAllowed = 1;
    cfg.attrs = at;
    cfg.numAttrs = 1;

    cudaError_t e = cudaLaunchKernelEx(&cfg, main_kernel,
                                       r, warm, Ts, rho, pi, (u64*)d_out, T, S);
    if (e != cudaSuccess) {
        // fallback: plain serial launch (identical to the R8 best path)
        main_kernel<<<grid, 128>>>(r, warm, Ts, rho, pi, (u64*)d_out, T, S);
    }
}